// round 8
// baseline (speedup 1.0000x reference)
#include <cuda_runtime.h>
#include <cstdint>

#define Bb 64
#define Tt 1024
#define Ii 64
#define Hh 512
#define G3 1536
#define MM (Bb*Tt)      // 65536 rows

// ---------------- scratch (device globals: allocation-free) ----------------
__device__ float g_xg[(size_t)MM * G3];   // input-side gates, reused per layer (~403 MB)
__device__ float g_y [(size_t)MM * Hh];   // layer output / hidden history (~134 MB)

struct __align__(128) PadCtr { unsigned v; unsigned pad[31]; };
__device__ PadCtr g_cnt[4];   // per-batch-group arrival counters (monotonic)
__device__ PadCtr g_gen[4];   // per-batch-group generation counters (monotonic)

// ---------------- helpers ----------------
__device__ __forceinline__ float to_tf32(float x) {
    unsigned u;
    asm("cvt.rna.tf32.f32 %0, %1;" : "=r"(u) : "f"(x));
    return __uint_as_float(u);
}

__device__ __forceinline__ void mma_tf32(float* c, const unsigned* a, unsigned b0, unsigned b1) {
    asm("mma.sync.aligned.m16n8k8.row.col.f32.tf32.tf32.f32 "
        "{%0,%1,%2,%3},{%4,%5,%6,%7},{%8,%9},{%0,%1,%2,%3};"
        : "+f"(c[0]), "+f"(c[1]), "+f"(c[2]), "+f"(c[3])
        : "r"(a[0]), "r"(a[1]), "r"(a[2]), "r"(a[3]), "r"(b0), "r"(b1));
}

// ---------------- generic tf32 GEMM: C[m][n] = sum_k A[m][k]*W[n][k] + bias[n] ----
// BM=128, BN=64, BK=16, 256 threads, 8 warps as 4x2 (each warp 32x32).
__global__ __launch_bounds__(256) void gemm_tf32(
    const float* __restrict__ A, const float* __restrict__ W,
    const float* __restrict__ bias, float* __restrict__ C,
    int M, int N, int K)
{
    __shared__ float As[128][20];
    __shared__ float Ws[64][20];
    const int tid  = threadIdx.x;
    const int warp = tid >> 5, lane = tid & 31;
    const int gID  = lane >> 2, tig = lane & 3;
    const int wm   = warp >> 1, wn = warp & 1;
    const int m0   = blockIdx.y * 128, n0 = blockIdx.x * 64;

    float acc[2][4][4];
    #pragma unroll
    for (int i = 0; i < 2; i++)
        #pragma unroll
        for (int j = 0; j < 4; j++)
            #pragma unroll
            for (int q = 0; q < 4; q++) acc[i][j][q] = 0.f;

    for (int k0 = 0; k0 < K; k0 += 16) {
        #pragma unroll
        for (int i = 0; i < 2; i++) {
            int idx = tid + i * 256;               // 0..511 float4s
            int r = idx >> 2, cb = idx & 3;
            float4 v = *(const float4*)(A + (size_t)(m0 + r) * K + k0 + cb * 4);
            *(float4*)(&As[r][cb * 4]) =
                make_float4(to_tf32(v.x), to_tf32(v.y), to_tf32(v.z), to_tf32(v.w));
        }
        {
            int r = tid >> 2, cb = tid & 3;        // 256 float4s
            float4 v = *(const float4*)(W + (size_t)(n0 + r) * K + k0 + cb * 4);
            *(float4*)(&Ws[r][cb * 4]) =
                make_float4(to_tf32(v.x), to_tf32(v.y), to_tf32(v.z), to_tf32(v.w));
        }
        __syncthreads();
        #pragma unroll
        for (int s = 0; s < 2; s++) {
            const int kk = s * 8;
            unsigned a[2][4];
            #pragma unroll
            for (int mt = 0; mt < 2; mt++) {
                int r = wm * 32 + mt * 16 + gID;
                a[mt][0] = __float_as_uint(As[r][kk + tig]);
                a[mt][1] = __float_as_uint(As[r + 8][kk + tig]);
                a[mt][2] = __float_as_uint(As[r][kk + tig + 4]);
                a[mt][3] = __float_as_uint(As[r + 8][kk + tig + 4]);
            }
            #pragma unroll
            for (int nt = 0; nt < 4; nt++) {
                int n = wn * 32 + nt * 8 + gID;
                unsigned b0 = __float_as_uint(Ws[n][kk + tig]);
                unsigned b1 = __float_as_uint(Ws[n][kk + tig + 4]);
                #pragma unroll
                for (int mt = 0; mt < 2; mt++)
                    mma_tf32(acc[mt][nt], a[mt], b0, b1);
            }
        }
        __syncthreads();
    }
    #pragma unroll
    for (int mt = 0; mt < 2; mt++) {
        int r0 = m0 + wm * 32 + mt * 16 + gID;
        #pragma unroll
        for (int nt = 0; nt < 4; nt++) {
            int c = n0 + wn * 32 + nt * 8 + tig * 2;
            float bc0 = bias[c], bc1 = bias[c + 1];
            C[(size_t)r0 * N + c]           = acc[mt][nt][0] + bc0;
            C[(size_t)r0 * N + c + 1]       = acc[mt][nt][1] + bc1;
            C[(size_t)(r0 + 8) * N + c]     = acc[mt][nt][2] + bc0;
            C[(size_t)(r0 + 8) * N + c + 1] = acc[mt][nt][3] + bc1;
        }
    }
}

// ---------------- persistent recurrent kernel ----------------
// 128 blocks: bid&3 = batch group (16 batches), bid>>2 = hidden block (16 units).
// Weights slice (48 rows x 512) lives in smem for the whole kernel.
#define RPAD 516
#define RROWS 48

__global__ __launch_bounds__(256, 1) void gru_rec(
    const float* __restrict__ xg, const float* __restrict__ whh,
    const float* __restrict__ bhh, float* __restrict__ y)
{
    extern __shared__ float sm[];
    float* w_s  = sm;                      // 48*516
    float* h_s  = w_s + RROWS * RPAD;      // 16*516
    float* part = h_s + 16 * RPAD;         // 8*16*48
    float* b_s  = part + 8 * 16 * 48;      // 48

    const int bid  = blockIdx.x;
    const int grp  = bid & 3;
    const int hb   = bid >> 2;
    const int tid  = threadIdx.x;
    const int warp = tid >> 5, lane = tid & 31;
    const int gID  = lane >> 2, tig = lane & 3;
    const int bb   = tid >> 4, uu = tid & 15;
    const int bglob = grp * 16;

    // load this block's W_hh slice (rows: 16 r-gate, 16 z-gate, 16 n-gate), tf32-rounded
    for (int idx = tid; idx < RROWS * (Hh / 4); idx += 256) {
        int j = idx >> 7;                  // row 0..47
        int cb = idx & 127;
        int gr = (j >> 4) * Hh + hb * 16 + (j & 15);
        float4 v = *(const float4*)(whh + (size_t)gr * Hh + cb * 4);
        *(float4*)(w_s + j * RPAD + cb * 4) =
            make_float4(to_tf32(v.x), to_tf32(v.y), to_tf32(v.z), to_tf32(v.w));
    }
    if (tid < RROWS) b_s[tid] = bhh[(tid >> 4) * Hh + hb * 16 + (tid & 15)];
    for (int idx = tid; idx < 16 * RPAD; idx += 256) h_s[idx] = 0.f;   // h_0 = 0

    unsigned gen0 = 0;
    if (tid == 0) gen0 = *(volatile unsigned*)&g_gen[grp].v;  // stable: prior launch done;
    __syncthreads();  // this launch's first increment needs all 32 blocks to have arrived

    for (int t = 0; t < Tt; t++) {
        if (t > 0) {
            #pragma unroll
            for (int i = 0; i < 8; i++) {
                int idx = tid + i * 256;   // 2048 float4s = 16x512
                int r = idx >> 7, cb = idx & 127;
                float4 v = *(const float4*)(y + ((size_t)(bglob + r) * Tt + (t - 1)) * Hh + cb * 4);
                *(float4*)(h_s + r * RPAD + cb * 4) =
                    make_float4(to_tf32(v.x), to_tf32(v.y), to_tf32(v.z), to_tf32(v.w));
            }
        }
        __syncthreads();

        // hg partial = h[16 x k-chunk] * W^T : warp owns k-range [warp*64, +64)
        float acc[6][4];
        #pragma unroll
        for (int nt = 0; nt < 6; nt++) { acc[nt][0]=acc[nt][1]=acc[nt][2]=acc[nt][3]=0.f; }
        const int k0w = warp * 64;
        #pragma unroll
        for (int ks = 0; ks < 8; ks++) {
            int k = k0w + ks * 8;
            unsigned a[4];
            a[0] = __float_as_uint(h_s[gID * RPAD + k + tig]);
            a[1] = __float_as_uint(h_s[(gID + 8) * RPAD + k + tig]);
            a[2] = __float_as_uint(h_s[gID * RPAD + k + tig + 4]);
            a[3] = __float_as_uint(h_s[(gID + 8) * RPAD + k + tig + 4]);
            #pragma unroll
            for (int nt = 0; nt < 6; nt++) {
                unsigned b0 = __float_as_uint(w_s[(nt * 8 + gID) * RPAD + k + tig]);
                unsigned b1 = __float_as_uint(w_s[(nt * 8 + gID) * RPAD + k + tig + 4]);
                mma_tf32(acc[nt], a, b0, b1);
            }
        }
        float* pw = part + warp * 768;
        #pragma unroll
        for (int nt = 0; nt < 6; nt++) {
            int c = nt * 8 + tig * 2;
            pw[gID * 48 + c]           = acc[nt][0];
            pw[gID * 48 + c + 1]       = acc[nt][1];
            pw[(gID + 8) * 48 + c]     = acc[nt][2];
            pw[(gID + 8) * 48 + c + 1] = acc[nt][3];
        }
        __syncthreads();

        // gates: one (batch, unit) output per thread; fold 8-way k-reduction here
        float hr = b_s[uu], hz = b_s[16 + uu], hn = b_s[32 + uu];
        #pragma unroll
        for (int w = 0; w < 8; w++) {
            const float* p = part + w * 768 + bb * 48;
            hr += p[uu]; hz += p[16 + uu]; hn += p[32 + uu];
        }
        const int b  = bglob + bb;
        const int ug = hb * 16 + uu;
        const size_t xb = ((size_t)b * Tt + t) * (size_t)G3;
        float rr = xg[xb + ug] + hr;
        float zz = xg[xb + Hh + ug] + hz;
        float xn = xg[xb + 2 * Hh + ug];
        float r = 1.f / (1.f + __expf(-rr));
        float z = 1.f / (1.f + __expf(-zz));
        float n = tanhf(xn + r * hn);
        float hp = h_s[bb * RPAD + ug];            // h_{t-1} (tf32-rounded: ~1e-4 rel)
        float hnew = (1.f - z) * n + z * hp;
        y[((size_t)b * Tt + t) * Hh + ug] = hnew;

        // 32-block barrier within this batch group (monotonic gen, replay-safe)
        if (t < Tt - 1) {
            __syncthreads();
            if (tid == 0) {
                __threadfence();
                unsigned arr = atomicAdd(&g_cnt[grp].v, 1u);
                if ((arr & 31u) == 31u) {
                    atomicAdd(&g_gen[grp].v, 1u);
                } else {
                    unsigned target = gen0 + (unsigned)t + 1u;
                    while ((int)(*(volatile unsigned*)&g_gen[grp].v - target) < 0)
                        __nanosleep(40);
                }
                __threadfence();
            }
            __syncthreads();
        }
    }
}

// ---------------- launch ----------------
extern "C" void kernel_launch(void* const* d_in, const int* in_sizes, int n_in,
                              void* d_out, int out_size)
{
    const float* x    = (const float*)d_in[0];
    const float* wih0 = (const float*)d_in[1];
    const float* whh0 = (const float*)d_in[2];
    const float* bih0 = (const float*)d_in[3];
    const float* bhh0 = (const float*)d_in[4];
    const float* wih1 = (const float*)d_in[5];
    const float* whh1 = (const float*)d_in[6];
    const float* bih1 = (const float*)d_in[7];
    const float* bhh1 = (const float*)d_in[8];
    const float* fcw  = (const float*)d_in[9];
    const float* fcb  = (const float*)d_in[10];
    float* out = (float*)d_out;

    float *xgp = 0, *yp = 0;
    cudaGetSymbolAddress((void**)&xgp, g_xg);
    cudaGetSymbolAddress((void**)&yp,  g_y);

    const size_t rec_smem = (size_t)(64 * RPAD + 8 * 16 * 48 + 48) * sizeof(float); // 156,864 B
    cudaFuncSetAttribute(gru_rec, cudaFuncAttributeMaxDynamicSharedMemorySize, (int)rec_smem);

    // layer 0: xg0 = x @ w_ih0^T + b_ih0   (K=64)
    gemm_tf32<<<dim3(G3 / 64, MM / 128), 256>>>(x, wih0, bih0, xgp, MM, G3, Ii);
    // layer 0 recurrence -> y
    gru_rec<<<128, 256, rec_smem>>>(xgp, whh0, bhh0, yp);
    // layer 1: xg1 = y0 @ w_ih1^T + b_ih1  (K=512) — reuses g_xg after layer-0 loop is done
    gemm_tf32<<<dim3(G3 / 64, MM / 128), 256>>>(yp, wih1, bih1, xgp, MM, G3, Hh);
    // layer 1 recurrence -> y (overwrites y0, which is dead after xg1)
    gru_rec<<<128, 256, rec_smem>>>(xgp, whh1, bhh1, yp);
    // FC: out = y1 @ fc_w^T + fc_b (N=64)
    gemm_tf32<<<dim3(Ii / 64, MM / 128), 256>>>(yp, fcw, fcb, out, MM, Ii, Hh);
}